// round 5
// baseline (speedup 1.0000x reference)
#include <cuda_runtime.h>
#include <cuda_bf16.h>
#include <cstdint>
#include <cstddef>

// Problem dims (fixed by the reference)
#define M_DIM 8192
#define N_DIM 1024
#define K_IN  512
#define K_DIM 1536           // K_IN + 1024 (recurrent)
#define PLANE ((size_t)M_DIM * N_DIM)

// GEMM tiling
#define BM 128
#define BN 128
#define BK 32
#define PAD 40                       // halves per smem row (32 data + 8 pad, conflict-free for ldmatrix)
#define TILE_H (BM * PAD)            // halves per tile
#define STAGE_H (3 * TILE_H)         // A + Bhi + Blo
#define SMEM_BYTES (2 * STAGE_H * 2) // 2 stages * halves * 2B = 61440

// Scratch (no cudaMalloc allowed)
__device__ __nv_bfloat16 g_A [(size_t)M_DIM * K_DIM];  // ~25.2 MB
__device__ __nv_bfloat16 g_Bh[(size_t)N_DIM * K_DIM];  // 3 MB
__device__ __nv_bfloat16 g_Bl[(size_t)N_DIM * K_DIM];  // 3 MB

// ---------------------------------------------------------------------------
// helpers
// ---------------------------------------------------------------------------
__device__ __forceinline__ void cp16(__nv_bfloat16* s, const __nv_bfloat16* g) {
    uint32_t sa = (uint32_t)__cvta_generic_to_shared(s);
    asm volatile("cp.async.cg.shared.global [%0], [%1], 16;\n" :: "r"(sa), "l"(g));
}
__device__ __forceinline__ void ldm_x4(uint32_t* r, const __nv_bfloat16* p) {
    uint32_t a = (uint32_t)__cvta_generic_to_shared(p);
    asm volatile("ldmatrix.sync.aligned.m8n8.x4.shared.b16 {%0,%1,%2,%3}, [%4];\n"
        : "=r"(r[0]), "=r"(r[1]), "=r"(r[2]), "=r"(r[3]) : "r"(a));
}
__device__ __forceinline__ void ldm_x2(uint32_t* r, const __nv_bfloat16* p) {
    uint32_t a = (uint32_t)__cvta_generic_to_shared(p);
    asm volatile("ldmatrix.sync.aligned.m8n8.x2.shared.b16 {%0,%1}, [%2];\n"
        : "=r"(r[0]), "=r"(r[1]) : "r"(a));
}
__device__ __forceinline__ void mma_bf16(float* c, const uint32_t* a, const uint32_t* b) {
    asm volatile("mma.sync.aligned.m16n8k16.row.col.f32.bf16.bf16.f32 "
        "{%0,%1,%2,%3}, {%4,%5,%6,%7}, {%8,%9}, {%0,%1,%2,%3};\n"
        : "+f"(c[0]), "+f"(c[1]), "+f"(c[2]), "+f"(c[3])
        : "r"(a[0]), "r"(a[1]), "r"(a[2]), "r"(a[3]), "r"(b[0]), "r"(b[1]));
}

// ---------------------------------------------------------------------------
// pack kernels: build bf16 A = [spikes | z], split-bf16 B = [Win | Wrec]
// ---------------------------------------------------------------------------
__global__ void pack_A_kernel(const float* __restrict__ sp, const float* __restrict__ z) {
    size_t g = (size_t)blockIdx.x * blockDim.x + threadIdx.x;   // one group of 4 cols
    int row = (int)(g / (K_DIM / 4));
    int col = (int)(g % (K_DIM / 4)) * 4;
    float4 v = (col < K_IN)
        ? *(const float4*)(sp + (size_t)row * K_IN + col)
        : *(const float4*)(z  + (size_t)row * (K_DIM - K_IN) + (col - K_IN));
    __nv_bfloat162 p0 = __floats2bfloat162_rn(v.x, v.y);
    __nv_bfloat162 p1 = __floats2bfloat162_rn(v.z, v.w);
    __nv_bfloat162* dst = (__nv_bfloat162*)(g_A + (size_t)row * K_DIM + col);
    dst[0] = p0; dst[1] = p1;
}

__global__ void pack_B_kernel(const float* __restrict__ wi, const float* __restrict__ wr) {
    size_t g = (size_t)blockIdx.x * blockDim.x + threadIdx.x;   // one element
    int row = (int)(g / K_DIM);
    int col = (int)(g % K_DIM);
    float w = (col < K_IN) ? wi[(size_t)row * K_IN + col]
                           : wr[(size_t)row * (K_DIM - K_IN) + (col - K_IN)];
    __nv_bfloat16 hi = __float2bfloat16(w);
    float lo = w - __bfloat162float(hi);   // exact residual
    g_Bh[g] = hi;
    g_Bl[g] = __float2bfloat16(lo);
}

// ---------------------------------------------------------------------------
// pointwise: z_new, v_new, b_new planes (exact fp32, reference op order)
// ---------------------------------------------------------------------------
__device__ __forceinline__ void lsnn_pw(float v, float i, float b,
                                        float& z, float& vn, float& bn) {
    // v_decayed = v + 0.1 * ((0 - v) + i)
    float t  = __fadd_rn(-v, i);
    float vd = __fadd_rn(v, __fmul_rn(0.1f, t));
    // b_decayed = b + 1.25e-6 * (1 - b)
    float bd = __fadd_rn(b, __fmul_rn(1.25e-6f, __fsub_rn(1.0f, b)));
    z  = (__fsub_rn(vd, bd) > 0.0f) ? 1.0f : 0.0f;
    vn = (z > 0.0f) ? 0.0f : vd;                       // (1-z)*vd + z*0
    bn = __fadd_rn(bd, __fmul_rn(__fmul_rn(z, 0.00125f), 1.8f));
}

__global__ void pointwise_kernel(const float* __restrict__ v, const float* __restrict__ i_,
                                 const float* __restrict__ b_, float* __restrict__ out) {
    size_t g = ((size_t)blockIdx.x * blockDim.x + threadIdx.x) * 4;
    float4 v4 = *(const float4*)(v  + g);
    float4 i4 = *(const float4*)(i_ + g);
    float4 b4 = *(const float4*)(b_ + g);
    float4 z4, vn4, bn4;
    lsnn_pw(v4.x, i4.x, b4.x, z4.x, vn4.x, bn4.x);
    lsnn_pw(v4.y, i4.y, b4.y, z4.y, vn4.y, bn4.y);
    lsnn_pw(v4.z, i4.z, b4.z, z4.z, vn4.z, bn4.z);
    lsnn_pw(v4.w, i4.w, b4.w, z4.w, vn4.w, bn4.w);
    *(float4*)(out + g)             = z4;               // plane 0: z_new
    *(float4*)(out + PLANE + g)     = vn4;              // plane 1: v_new
    *(float4*)(out + 3 * PLANE + g) = bn4;              // plane 3: b_new
}

// ---------------------------------------------------------------------------
// fused GEMM: S = A @ (Bhi + Blo)^T, out_i = i*0.8 + S   (plane 2)
// 128x128 CTA tile, 8 warps of 64x32, cp.async double buffer, bf16 mma
// ---------------------------------------------------------------------------
__global__ void __launch_bounds__(256) lsnn_gemm(const float* __restrict__ Icur,
                                                 float* __restrict__ outI) {
    extern __shared__ __align__(16) __nv_bfloat16 smem[];
    const int tid  = threadIdx.x;
    const int lane = tid & 31;
    const int warp = tid >> 5;
    const int wm   = warp & 1;     // warp row (2)
    const int wn   = warp >> 1;    // warp col (4)
    const int bm   = blockIdx.y;
    const int bn   = blockIdx.x;

    float c[4][4][4];
    #pragma unroll
    for (int a = 0; a < 4; a++)
        #pragma unroll
        for (int b = 0; b < 4; b++)
            #pragma unroll
            for (int d = 0; d < 4; d++) c[a][b][d] = 0.0f;

    auto load_tiles = [&](int s, int kt) {
        __nv_bfloat16* As = smem + s * STAGE_H;
        __nv_bfloat16* Bh = As + TILE_H;
        __nv_bfloat16* Bl = Bh + TILE_H;
        const int k0 = kt * BK;
        #pragma unroll
        for (int i = 0; i < 2; i++) {
            int ch  = tid + i * 256;       // 512 16B-chunks per tile
            int row = ch >> 2;
            int cc  = (ch & 3) * 8;        // halves
            cp16(As + row * PAD + cc, g_A  + (size_t)(bm * BM + row) * K_DIM + k0 + cc);
            cp16(Bh + row * PAD + cc, g_Bh + (size_t)(bn * BN + row) * K_DIM + k0 + cc);
            cp16(Bl + row * PAD + cc, g_Bl + (size_t)(bn * BN + row) * K_DIM + k0 + cc);
        }
        asm volatile("cp.async.commit_group;\n" ::);
    };

    load_tiles(0, 0);
    const int KT = K_DIM / BK;   // 48
    for (int kt = 0; kt < KT; ++kt) {
        if (kt + 1 < KT) {
            load_tiles((kt + 1) & 1, kt + 1);
            asm volatile("cp.async.wait_group 1;\n" ::);
        } else {
            asm volatile("cp.async.wait_group 0;\n" ::);
        }
        __syncthreads();

        const __nv_bfloat16* As = smem + (kt & 1) * STAGE_H;
        const __nv_bfloat16* Bh = As + TILE_H;
        const __nv_bfloat16* Bl = Bh + TILE_H;
        #pragma unroll
        for (int ks = 0; ks < 2; ++ks) {   // two k16 sub-steps per BK=32
            uint32_t af[4][4];
            #pragma unroll
            for (int mi = 0; mi < 4; ++mi) {
                const __nv_bfloat16* p = As + (wm * 64 + mi * 16 + (lane & 15)) * PAD
                                            + ks * 16 + (lane >> 4) * 8;
                ldm_x4(af[mi], p);
            }
            uint32_t bhf[4][2], blf[4][2];
            #pragma unroll
            for (int ni = 0; ni < 4; ++ni) {
                int r = lane & 15;
                const __nv_bfloat16* ph = Bh + (wn * 32 + ni * 8 + (r & 7)) * PAD
                                             + ks * 16 + (r >> 3) * 8;
                ldm_x2(bhf[ni], ph);
                const __nv_bfloat16* pl = Bl + (wn * 32 + ni * 8 + (r & 7)) * PAD
                                             + ks * 16 + (r >> 3) * 8;
                ldm_x2(blf[ni], pl);
            }
            #pragma unroll
            for (int mi = 0; mi < 4; ++mi)
                #pragma unroll
                for (int ni = 0; ni < 4; ++ni) {
                    mma_bf16(c[mi][ni], af[mi], bhf[ni]);   // hi part
                    mma_bf16(c[mi][ni], af[mi], blf[ni]);   // lo residual
                }
        }
        __syncthreads();
    }

    // epilogue: i_new = (i + (-0.2)*i) + S
    #pragma unroll
    for (int mi = 0; mi < 4; ++mi) {
        int row0 = bm * BM + wm * 64 + mi * 16 + (lane >> 2);
        #pragma unroll
        for (int ni = 0; ni < 4; ++ni) {
            int col = bn * BN + wn * 32 + ni * 8 + (lane & 3) * 2;
            size_t i0 = (size_t)row0 * N_DIM + col;
            size_t i1 = i0 + (size_t)8 * N_DIM;
            float x0 = Icur[i0], x1 = Icur[i0 + 1], x2 = Icur[i1], x3 = Icur[i1 + 1];
            outI[i0]     = fmaf(-0.2f, x0, x0) + c[mi][ni][0];
            outI[i0 + 1] = fmaf(-0.2f, x1, x1) + c[mi][ni][1];
            outI[i1]     = fmaf(-0.2f, x2, x2) + c[mi][ni][2];
            outI[i1 + 1] = fmaf(-0.2f, x3, x3) + c[mi][ni][3];
        }
    }
}

// ---------------------------------------------------------------------------
// entry
// ---------------------------------------------------------------------------
extern "C" void kernel_launch(void* const* d_in, const int* in_sizes, int n_in,
                              void* d_out, int out_size) {
    const float* spikes = (const float*)d_in[0];   // [8192, 512]
    const float* z      = (const float*)d_in[1];   // [8192, 1024]
    const float* v      = (const float*)d_in[2];   // [8192, 1024]
    const float* i_     = (const float*)d_in[3];   // [8192, 1024]
    const float* b      = (const float*)d_in[4];   // [8192, 1024]
    const float* wi     = (const float*)d_in[5];   // [1024, 512]
    const float* wr     = (const float*)d_in[6];   // [1024, 1024]
    float* out = (float*)d_out;                    // [4, 8192, 1024]

    cudaFuncSetAttribute(lsnn_gemm, cudaFuncAttributeMaxDynamicSharedMemorySize, SMEM_BYTES);

    pack_A_kernel<<<(M_DIM * K_DIM / 4) / 256, 256>>>(spikes, z);     // 12288 blocks
    pack_B_kernel<<<(N_DIM * K_DIM) / 256, 256>>>(wi, wr);            // 6144 blocks
    pointwise_kernel<<<(int)(PLANE / 4 / 256), 256>>>(v, i_, b, out); // 8192 blocks

    dim3 grid(N_DIM / BN, M_DIM / BM);   // (8, 64)
    lsnn_gemm<<<grid, 256, SMEM_BYTES>>>(i_, out + 2 * PLANE);
}

// round 13
// speedup vs baseline: 1.1008x; 1.1008x over previous
#include <cuda_runtime.h>
#include <cuda_bf16.h>
#include <cstdint>
#include <cstddef>

// Problem dims (fixed by the reference)
#define M_DIM 8192
#define N_DIM 1024
#define K_IN  512
#define K_DIM 1536           // K_IN + 1024 (recurrent)
#define PLANE ((size_t)M_DIM * N_DIM)

// GEMM tiling (legacy HMMA path — tcgen05 PTX is rejected by this harness's
// compute_103 target, confirmed by ptxas in round 9)
#define BM 128
#define BN 128
#define BK 32
#define PAD 40                       // halves per smem row (32 data + 8 pad, conflict-free ldmatrix)
#define TILE_H (BM * PAD)            // halves per tile (5120)
#define STAGE_H (3 * TILE_H)         // A + Bhi + Blo   (15360 halves = 30720 B)
#define N_STAGES 3
#define SMEM_BYTES (N_STAGES * STAGE_H * 2)   // 92160 B -> 2 CTAs/SM

// Scratch (no cudaMalloc allowed)
__device__ __nv_bfloat16 g_A [(size_t)M_DIM * K_DIM];  // ~25.2 MB
__device__ __nv_bfloat16 g_Bh[(size_t)N_DIM * K_DIM];  // 3 MB
__device__ __nv_bfloat16 g_Bl[(size_t)N_DIM * K_DIM];  // 3 MB

// ---------------------------------------------------------------------------
// helpers
// ---------------------------------------------------------------------------
__device__ __forceinline__ void cp16(__nv_bfloat16* s, const __nv_bfloat16* g) {
    uint32_t sa = (uint32_t)__cvta_generic_to_shared(s);
    asm volatile("cp.async.cg.shared.global [%0], [%1], 16;\n" :: "r"(sa), "l"(g));
}
__device__ __forceinline__ void ldm_x4(uint32_t* r, const __nv_bfloat16* p) {
    uint32_t a = (uint32_t)__cvta_generic_to_shared(p);
    asm volatile("ldmatrix.sync.aligned.m8n8.x4.shared.b16 {%0,%1,%2,%3}, [%4];\n"
        : "=r"(r[0]), "=r"(r[1]), "=r"(r[2]), "=r"(r[3]) : "r"(a));
}
__device__ __forceinline__ void ldm_x2(uint32_t* r, const __nv_bfloat16* p) {
    uint32_t a = (uint32_t)__cvta_generic_to_shared(p);
    asm volatile("ldmatrix.sync.aligned.m8n8.x2.shared.b16 {%0,%1}, [%2];\n"
        : "=r"(r[0]), "=r"(r[1]) : "r"(a));
}
__device__ __forceinline__ void mma_bf16(float* c, const uint32_t* a, const uint32_t* b) {
    asm volatile("mma.sync.aligned.m16n8k16.row.col.f32.bf16.bf16.f32 "
        "{%0,%1,%2,%3}, {%4,%5,%6,%7}, {%8,%9}, {%0,%1,%2,%3};\n"
        : "+f"(c[0]), "+f"(c[1]), "+f"(c[2]), "+f"(c[3])
        : "r"(a[0]), "r"(a[1]), "r"(a[2]), "r"(a[3]), "r"(b[0]), "r"(b[1]));
}

// ---------------------------------------------------------------------------
// pack kernels: build bf16 A = [spikes | z], split-bf16 B = [Win | Wrec]
// ---------------------------------------------------------------------------
__global__ void pack_A_kernel(const float* __restrict__ sp, const float* __restrict__ z) {
    size_t g = (size_t)blockIdx.x * blockDim.x + threadIdx.x;   // one group of 4 cols
    int row = (int)(g / (K_DIM / 4));
    int col = (int)(g % (K_DIM / 4)) * 4;
    float4 v = (col < K_IN)
        ? *(const float4*)(sp + (size_t)row * K_IN + col)
        : *(const float4*)(z  + (size_t)row * (K_DIM - K_IN) + (col - K_IN));
    __nv_bfloat162 p0 = __floats2bfloat162_rn(v.x, v.y);
    __nv_bfloat162 p1 = __floats2bfloat162_rn(v.z, v.w);
    __nv_bfloat162* dst = (__nv_bfloat162*)(g_A + (size_t)row * K_DIM + col);
    dst[0] = p0; dst[1] = p1;
}

__global__ void pack_B_kernel(const float* __restrict__ wi, const float* __restrict__ wr) {
    size_t g = (size_t)blockIdx.x * blockDim.x + threadIdx.x;   // one element
    int row = (int)(g / K_DIM);
    int col = (int)(g % K_DIM);
    float w = (col < K_IN) ? wi[(size_t)row * K_IN + col]
                           : wr[(size_t)row * (K_DIM - K_IN) + (col - K_IN)];
    __nv_bfloat16 hi = __float2bfloat16(w);
    float lo = w - __bfloat162float(hi);   // exact residual
    g_Bh[g] = hi;
    g_Bl[g] = __float2bfloat16(lo);
}

// ---------------------------------------------------------------------------
// pointwise math (exact fp32, reference op order — no FMA contraction)
// ---------------------------------------------------------------------------
__device__ __forceinline__ void lsnn_pw(float v, float i, float b,
                                        float& z, float& vn, float& bn) {
    float t  = __fadd_rn(-v, i);
    float vd = __fadd_rn(v, __fmul_rn(0.1f, t));
    float bd = __fadd_rn(b, __fmul_rn(1.25e-6f, __fsub_rn(1.0f, b)));
    z  = (__fsub_rn(vd, bd) > 0.0f) ? 1.0f : 0.0f;
    vn = (z > 0.0f) ? 0.0f : vd;
    bn = __fadd_rn(bd, __fmul_rn(__fmul_rn(z, 0.00125f), 1.8f));
}

// ---------------------------------------------------------------------------
// fused GEMM + pointwise:
//   S = A @ (Bhi + Blo)^T  (fp32 accum, split-bf16)
//   epilogue per element: z/v/b planes + i_new = i*0.8 + S
// 128x128 CTA tile, 8 warps of 64x32, 3-stage cp.async ring (1 sync/iter)
// ---------------------------------------------------------------------------
__global__ void __launch_bounds__(256, 2) lsnn_gemm(const float* __restrict__ Vin,
                                                    const float* __restrict__ Iin,
                                                    const float* __restrict__ Bin,
                                                    float* __restrict__ out) {
    extern __shared__ __align__(16) __nv_bfloat16 smem[];
    const int tid  = threadIdx.x;
    const int lane = tid & 31;
    const int warp = tid >> 5;
    const int wm   = warp & 1;     // warp row (2)
    const int wn   = warp >> 1;    // warp col (4)
    const int bm   = blockIdx.y;
    const int bn   = blockIdx.x;

    float c[4][4][4];
    #pragma unroll
    for (int a = 0; a < 4; a++)
        #pragma unroll
        for (int b = 0; b < 4; b++)
            #pragma unroll
            for (int d = 0; d < 4; d++) c[a][b][d] = 0.0f;

    auto load_tiles = [&](int kt) {
        __nv_bfloat16* As = smem + (kt % N_STAGES) * STAGE_H;
        __nv_bfloat16* Bh = As + TILE_H;
        __nv_bfloat16* Bl = Bh + TILE_H;
        const int k0 = kt * BK;
        #pragma unroll
        for (int i = 0; i < 2; i++) {
            int ch  = tid + i * 256;       // 512 16B-chunks per tile
            int row = ch >> 2;
            int cc  = (ch & 3) * 8;        // halves
            cp16(As + row * PAD + cc, g_A  + (size_t)(bm * BM + row) * K_DIM + k0 + cc);
            cp16(Bh + row * PAD + cc, g_Bh + (size_t)(bn * BN + row) * K_DIM + k0 + cc);
            cp16(Bl + row * PAD + cc, g_Bl + (size_t)(bn * BN + row) * K_DIM + k0 + cc);
        }
        asm volatile("cp.async.commit_group;\n" ::);
    };

    const int KT = K_DIM / BK;   // 48
    load_tiles(0);
    load_tiles(1);

    for (int kt = 0; kt < KT; ++kt) {
        if (kt + 1 < KT) asm volatile("cp.async.wait_group 1;\n" ::);
        else             asm volatile("cp.async.wait_group 0;\n" ::);
        __syncthreads();
        if (kt + 2 < KT) load_tiles(kt + 2);   // writes stage (kt+2)%3 == (kt-1)%3, consumed last iter

        const __nv_bfloat16* As = smem + (kt % N_STAGES) * STAGE_H;
        const __nv_bfloat16* Bh = As + TILE_H;
        const __nv_bfloat16* Bl = Bh + TILE_H;
        #pragma unroll
        for (int ks = 0; ks < 2; ++ks) {   // two k16 sub-steps per BK=32
            uint32_t af[4][4];
            #pragma unroll
            for (int mi = 0; mi < 4; ++mi) {
                const __nv_bfloat16* p = As + (wm * 64 + mi * 16 + (lane & 15)) * PAD
                                            + ks * 16 + (lane >> 4) * 8;
                ldm_x4(af[mi], p);
            }
            uint32_t bhf[4][2], blf[4][2];
            #pragma unroll
            for (int ni = 0; ni < 4; ++ni) {
                int r = lane & 15;
                const __nv_bfloat16* ph = Bh + (wn * 32 + ni * 8 + (r & 7)) * PAD
                                             + ks * 16 + (r >> 3) * 8;
                ldm_x2(bhf[ni], ph);
                const __nv_bfloat16* pl = Bl + (wn * 32 + ni * 8 + (r & 7)) * PAD
                                             + ks * 16 + (r >> 3) * 8;
                ldm_x2(blf[ni], pl);
            }
            // hi pass then lo pass: accumulator reuse distance = 16 MMAs
            #pragma unroll
            for (int mi = 0; mi < 4; ++mi)
                #pragma unroll
                for (int ni = 0; ni < 4; ++ni)
                    mma_bf16(c[mi][ni], af[mi], bhf[ni]);
            #pragma unroll
            for (int mi = 0; mi < 4; ++mi)
                #pragma unroll
                for (int ni = 0; ni < 4; ++ni)
                    mma_bf16(c[mi][ni], af[mi], blf[ni]);
        }
    }

    // ---- fused epilogue: pointwise planes + i_new ----
    #pragma unroll
    for (int mi = 0; mi < 4; ++mi) {
        #pragma unroll
        for (int half = 0; half < 2; ++half) {
            int row = bm * BM + wm * 64 + mi * 16 + (lane >> 2) + half * 8;
            #pragma unroll
            for (int ni = 0; ni < 4; ++ni) {
                int col = bn * BN + wn * 32 + ni * 8 + (lane & 3) * 2;
                size_t idx = (size_t)row * N_DIM + col;
                float2 vv = *(const float2*)(Vin + idx);
                float2 ii = *(const float2*)(Iin + idx);
                float2 bb = *(const float2*)(Bin + idx);
                float z0, vn0, bn0, z1, vn1, bn1;
                lsnn_pw(vv.x, ii.x, bb.x, z0, vn0, bn0);
                lsnn_pw(vv.y, ii.y, bb.y, z1, vn1, bn1);
                float2 zz = {z0, z1};
                float2 vo = {vn0, vn1};
                float2 io = {fmaf(-0.2f, ii.x, ii.x) + c[mi][ni][half * 2 + 0],
                             fmaf(-0.2f, ii.y, ii.y) + c[mi][ni][half * 2 + 1]};
                float2 bo = {bn0, bn1};
                *(float2*)(out + idx)             = zz;   // plane 0: z_new
                *(float2*)(out + PLANE + idx)     = vo;   // plane 1: v_new
                *(float2*)(out + 2 * PLANE + idx) = io;   // plane 2: i_new
                *(float2*)(out + 3 * PLANE + idx) = bo;   // plane 3: b_new
            }
        }
    }
}

// ---------------------------------------------------------------------------
// entry
// ---------------------------------------------------------------------------
extern "C" void kernel_launch(void* const* d_in, const int* in_sizes, int n_in,
                              void* d_out, int out_size) {
    const float* spikes = (const float*)d_in[0];   // [8192, 512]
    const float* z      = (const float*)d_in[1];   // [8192, 1024]
    const float* v      = (const float*)d_in[2];   // [8192, 1024]
    const float* i_     = (const float*)d_in[3];   // [8192, 1024]
    const float* b      = (const float*)d_in[4];   // [8192, 1024]
    const float* wi     = (const float*)d_in[5];   // [1024, 512]
    const float* wr     = (const float*)d_in[6];   // [1024, 1024]
    float* out = (float*)d_out;                    // [4, 8192, 1024]

    cudaFuncSetAttribute(lsnn_gemm, cudaFuncAttributeMaxDynamicSharedMemorySize, SMEM_BYTES);

    pack_A_kernel<<<(M_DIM * K_DIM / 4) / 256, 256>>>(spikes, z);
    pack_B_kernel<<<(N_DIM * K_DIM) / 256, 256>>>(wi, wr);

    dim3 grid(N_DIM / BN, M_DIM / BM);   // (8, 64)
    lsnn_gemm<<<grid, 256, SMEM_BYTES>>>(v, i_, b, out);
}